// round 1
// baseline (speedup 1.0000x reference)
#include <cuda_runtime.h>
#include <cuda_bf16.h>

#define N_NEURON 128
#define N_RULES  512
#define BATCH    4096

// Scratch for head activations: head[b][n], 4096 * 128 floats = 2 MB.
__device__ float g_head[BATCH * N_NEURON];

// Kernel 1: head[b,n] = x[n,b,:] . head_w[n,:] + head_b[n]
// One warp per (n,b) row. Row = 512 contiguous floats = 128 float4s.
// Lane l reads float4s at positions l, l+32, l+64, l+96 (coalesced).
__global__ void __launch_bounds__(256) lei_head_kernel(
    const float* __restrict__ x,
    const float* __restrict__ head_w,
    const float* __restrict__ head_b)
{
    const int warp_global = (blockIdx.x * blockDim.x + threadIdx.x) >> 5;
    const int lane = threadIdx.x & 31;

    // row id = n * BATCH + b ; consecutive warps share n -> head_w row is L1-hot
    const int n = warp_global >> 12;        // / 4096
    const int b = warp_global & (BATCH - 1);

    const float4* __restrict__ xrow =
        reinterpret_cast<const float4*>(x + (size_t)warp_global * N_RULES);
    const float4* __restrict__ wrow =
        reinterpret_cast<const float4*>(head_w + (size_t)n * N_RULES);

    float sum = 0.0f;
#pragma unroll
    for (int k = 0; k < 4; k++) {
        float4 xv = xrow[lane + 32 * k];
        float4 wv = wrow[lane + 32 * k];
        sum = fmaf(xv.x, wv.x, sum);
        sum = fmaf(xv.y, wv.y, sum);
        sum = fmaf(xv.z, wv.z, sum);
        sum = fmaf(xv.w, wv.w, sum);
    }

#pragma unroll
    for (int off = 16; off; off >>= 1)
        sum += __shfl_xor_sync(0xFFFFFFFFu, sum, off);

    if (lane == 0)
        g_head[b * N_NEURON + n] = sum + head_b[n];
}

// Kernel 2: logits[b,j] = head[b,:] . foot_w[j,:] + foot_b[j]; out = softmax(logits)
// One warp per batch element.
__global__ void __launch_bounds__(256) lei_foot_kernel(
    const float* __restrict__ foot_w,
    const float* __restrict__ foot_b,
    float* __restrict__ out)
{
    const int b = (blockIdx.x * blockDim.x + threadIdx.x) >> 5;
    const int lane = threadIdx.x & 31;
    if (b >= BATCH) return;

    const float4* __restrict__ h =
        reinterpret_cast<const float4*>(g_head + (size_t)b * N_NEURON);
    const float4* __restrict__ w0 = reinterpret_cast<const float4*>(foot_w);
    const float4* __restrict__ w1 = reinterpret_cast<const float4*>(foot_w + N_NEURON);

    float4 hv = h[lane];
    float4 a  = w0[lane];
    float4 c  = w1[lane];

    float s0 = hv.x * a.x + hv.y * a.y + hv.z * a.z + hv.w * a.w;
    float s1 = hv.x * c.x + hv.y * c.y + hv.z * c.z + hv.w * c.w;

#pragma unroll
    for (int off = 16; off; off >>= 1) {
        s0 += __shfl_xor_sync(0xFFFFFFFFu, s0, off);
        s1 += __shfl_xor_sync(0xFFFFFFFFu, s1, off);
    }

    if (lane == 0) {
        float l0 = s0 + foot_b[0];
        float l1 = s1 + foot_b[1];
        float m  = fmaxf(l0, l1);
        float e0 = __expf(l0 - m);
        float e1 = __expf(l1 - m);
        float inv = 1.0f / (e0 + e1);
        out[b * 2 + 0] = e0 * inv;
        out[b * 2 + 1] = e1 * inv;
    }
}

extern "C" void kernel_launch(void* const* d_in, const int* in_sizes, int n_in,
                              void* d_out, int out_size)
{
    const float* x      = (const float*)d_in[0];
    const float* head_w = (const float*)d_in[1];
    const float* head_b = (const float*)d_in[2];
    const float* foot_w = (const float*)d_in[3];
    const float* foot_b = (const float*)d_in[4];
    float* out = (float*)d_out;

    // Kernel 1: 128*4096 = 524288 warps, 8 warps/block -> 65536 blocks
    const int total_warps = N_NEURON * BATCH;
    lei_head_kernel<<<total_warps / 8, 256>>>(x, head_w, head_b);

    // Kernel 2: 4096 warps, 8 warps/block -> 512 blocks
    lei_foot_kernel<<<BATCH / 8, 256>>>(foot_w, foot_b, out);
}

// round 2
// speedup vs baseline: 1.0925x; 1.0925x over previous
#include <cuda_runtime.h>
#include <cuda_bf16.h>

#define N_NEURON 128
#define N_RULES  512
#define BATCH    4096

// Fully fused: one warp per batch element b.
// logit_j[b] = sum_n foot_w[j,n] * ( x[n,b,:].head_w[n,:] + head_b[n] ) + foot_b[j]
// Per-lane weighted accumulation; single warp-reduce at the end; softmax on lane 0.
__global__ void __launch_bounds__(128, 8) lei_fused_kernel(
    const float* __restrict__ x,
    const float* __restrict__ head_w,
    const float* __restrict__ head_b,
    const float* __restrict__ foot_w,
    const float* __restrict__ foot_b,
    float* __restrict__ out)
{
    const int warp = threadIdx.x >> 5;
    const int lane = threadIdx.x & 31;
    const int b = blockIdx.x * 4 + warp;   // 1024 blocks * 4 warps = 4096

    const float* __restrict__ fw0 = foot_w;            // [128]
    const float* __restrict__ fw1 = foot_w + N_NEURON; // [128]

    float acc0 = 0.0f, acc1 = 0.0f;

    // Fold the head bias contribution: sum_n head_b[n]*fw_j[n], split across lanes.
#pragma unroll
    for (int k = 0; k < 4; k++) {
        int n = 32 * k + lane;
        float hb = head_b[n];
        acc0 = fmaf(hb, fw0[n], acc0);
        acc1 = fmaf(hb, fw1[n], acc1);
    }

    const float4* __restrict__ xb =
        reinterpret_cast<const float4*>(x) + (size_t)b * (N_RULES / 4);
    const size_t nstride = (size_t)BATCH * (N_RULES / 4);  // float4 stride between neurons
    const float4* __restrict__ wq = reinterpret_cast<const float4*>(head_w);

    for (int n = 0; n < N_NEURON; n += 2) {
        // Front-batch 8 x loads (2 neurons' rows) for MLP.
        const float4* p0 = xb + (size_t)n * nstride;
        const float4* p1 = p0 + nstride;
        float4 xv[8];
#pragma unroll
        for (int k = 0; k < 4; k++) xv[k] = p0[lane + 32 * k];
#pragma unroll
        for (int k = 0; k < 4; k++) xv[4 + k] = p1[lane + 32 * k];

        float pa = 0.0f, pb = 0.0f;
#pragma unroll
        for (int k = 0; k < 4; k++) {
            float4 wv = wq[(size_t)n * (N_RULES / 4) + lane + 32 * k];
            pa = fmaf(xv[k].x, wv.x, pa);
            pa = fmaf(xv[k].y, wv.y, pa);
            pa = fmaf(xv[k].z, wv.z, pa);
            pa = fmaf(xv[k].w, wv.w, pa);
        }
#pragma unroll
        for (int k = 0; k < 4; k++) {
            float4 wv = wq[(size_t)(n + 1) * (N_RULES / 4) + lane + 32 * k];
            pb = fmaf(xv[4 + k].x, wv.x, pb);
            pb = fmaf(xv[4 + k].y, wv.y, pb);
            pb = fmaf(xv[4 + k].z, wv.z, pb);
            pb = fmaf(xv[4 + k].w, wv.w, pb);
        }

        acc0 = fmaf(pa, fw0[n], acc0);
        acc1 = fmaf(pa, fw1[n], acc1);
        acc0 = fmaf(pb, fw0[n + 1], acc0);
        acc1 = fmaf(pb, fw1[n + 1], acc1);
    }

    // Warp reduction of the two logit accumulators.
#pragma unroll
    for (int off = 16; off; off >>= 1) {
        acc0 += __shfl_xor_sync(0xFFFFFFFFu, acc0, off);
        acc1 += __shfl_xor_sync(0xFFFFFFFFu, acc1, off);
    }

    if (lane == 0) {
        float l0 = acc0 + foot_b[0];
        float l1 = acc1 + foot_b[1];
        float m = fmaxf(l0, l1);
        float e0 = __expf(l0 - m);
        float e1 = __expf(l1 - m);
        float inv = 1.0f / (e0 + e1);
        out[b * 2 + 0] = e0 * inv;
        out[b * 2 + 1] = e1 * inv;
    }
}

extern "C" void kernel_launch(void* const* d_in, const int* in_sizes, int n_in,
                              void* d_out, int out_size)
{
    const float* x      = (const float*)d_in[0];
    const float* head_w = (const float*)d_in[1];
    const float* head_b = (const float*)d_in[2];
    const float* foot_w = (const float*)d_in[3];
    const float* foot_b = (const float*)d_in[4];
    float* out = (float*)d_out;

    // 4096 warps total, one per batch element: 1024 blocks x 128 threads.
    lei_fused_kernel<<<BATCH / 4, 128>>>(x, head_w, head_b, foot_w, foot_b, out);
}